// round 7
// baseline (speedup 1.0000x reference)
#include <cuda_runtime.h>
#include <cstdint>
#include <cstddef>

#define LOG2E_F 1.4426950408889634f
#define LN2_F   0.6931471805599453f

__device__ __forceinline__ float ex2f_(float x) {
    float y; asm("ex2.approx.ftz.f32 %0, %1;" : "=f"(y) : "f"(x)); return y;
}
__device__ __forceinline__ float lg2f_(float x) {
    float y; asm("lg2.approx.f32 %0, %1;" : "=f"(y) : "f"(x)); return y;
}
__device__ __forceinline__ unsigned long long pk2(float lo, float hi) {
    unsigned long long r; asm("mov.b64 %0, {%1, %2};" : "=l"(r) : "f"(lo), "f"(hi)); return r;
}
__device__ __forceinline__ void upk2(unsigned long long v, float& lo, float& hi) {
    asm("mov.b64 {%0, %1}, %2;" : "=f"(lo), "=f"(hi) : "l"(v));
}
__device__ __forceinline__ void fma2_(unsigned long long& acc, unsigned long long a, unsigned long long b) {
    asm("fma.rn.f32x2 %0, %1, %2, %0;" : "+l"(acc) : "l"(a), "l"(b));
}
__device__ __forceinline__ unsigned long long add2_(unsigned long long a, unsigned long long b) {
    unsigned long long r; asm("add.rn.f32x2 %0, %1, %2;" : "=l"(r) : "l"(a), "l"(b)); return r;
}

// TWO batches per CTA, 512 threads. Threads [0,256) run batch 2*bid, threads
// [256,512) run batch 2*bid+1 — two fully independent recurrences whose
// serial chains (BAR -> LDS -> fma drain -> shfl -> STS) interleave in the
// SMSP schedulers, filling the ~73% idle issue slots measured in R3.
// Each 256-thread half uses R3's layout: lt>>2 -> column pair (j0, j0+1),
// ich = lt&3 -> 32-wide "from"-chunk; E-column-slices in registers as i-pair
// packed f32x2; 16 LDS.64 + 32 fma2 + 2 shfl per thread per step; forward
// vector linear-domain in double-buffered smem; exact power-of-2 renorm every
// 8 steps (publish t%8==0, fold t%8==1); one __syncthreads per step (couples
// the two symmetric halves, which is fine); obs via 4-deep prefetch ring.
__global__ __launch_bounds__(512, 1)
void crf_fwd_kernel(const float* __restrict__ obs,
                    const float* __restrict__ logA,
                    float* __restrict__ out,
                    int T, int B)
{
    constexpr int S  = 128;
    constexpr int CH = 34;     // chunk stride (floats): 8B-aligned, bank-skewed
    __shared__ __align__(16) float v_sm[2][2][4 * CH];   // [half][buf][...]
    __shared__ float wm[2][8];
    __shared__ float wsum[2][4];

    const int tid = threadIdx.x;
    const int h   = tid >> 8;          // batch half: 0 or 1
    const int lt  = tid & 255;         // local tid within half
    const int b   = min(2 * (int)blockIdx.x + h, B - 1);

    const int cp   = lt >> 2;
    const int ich  = lt & 3;
    const int j0   = cp * 2;
    const int lwrp = lt >> 5;          // warp index within half (0..7)
    const int wslot = ((j0 >> 5) * CH) + (j0 & 31);

    const float* ob = obs + (size_t)b * (size_t)T * S + j0;

    // A0[k] = {E[i0+2k][j0],   E[i0+2k+1][j0]}
    // A1[k] = {E[i0+2k][j0+1], E[i0+2k+1][j0+1]},  i0 = 32*ich
    unsigned long long A0[16], A1[16];
#pragma unroll
    for (int k = 0; k < 16; ++k) {
        const int i0 = ich * 32 + 2 * k;
        const float2 ea = *reinterpret_cast<const float2*>(logA + (size_t)i0 * S + j0);
        const float2 eb = *reinterpret_cast<const float2*>(logA + (size_t)(i0 + 1) * S + j0);
        A0[k] = pk2(ex2f_(ea.x * LOG2E_F), ex2f_(eb.x * LOG2E_F));
        A1[k] = pk2(ex2f_(ea.y * LOG2E_F), ex2f_(eb.y * LOG2E_F));
    }

    // ---- t = 0 (t%8==0): u = exp(obs[0]) raw; publish half-block max ----
    const float2 o0 = *reinterpret_cast<const float2*>(ob);
    const float u0 = ex2f_(o0.x * LOG2E_F);
    const float u1 = ex2f_(o0.y * LOG2E_F);
    {
        const int im = __reduce_max_sync(0xffffffffu, __float_as_int(fmaxf(u0, u1)));
        if ((lt & 31) == 0) wm[h][lwrp] = __int_as_float(im);
        if (ich == 0) {
            float2 w; w.x = u0; w.y = u1;
            *reinterpret_cast<float2*>(&v_sm[h][0][wslot]) = w;
        }
    }

    // 4-deep obs prefetch ring: oR[t & 3] holds obs[t].
    float2 oR[4];
#pragma unroll
    for (int k = 1; k <= 4; ++k)
        oR[k & 3] = (k < T) ? __ldcs(reinterpret_cast<const float2*>(ob + (size_t)k * S)) : o0;

    int L = 0;                 // exact accumulated log2 scale (uniform per half)
    __syncthreads();

    // ---- scan t = 1 .. T-1, ONE barrier per step ----
#pragma unroll 2
    for (int t = 1; t < T; ++t) {
        const int cb = (t - 1) & 1, nb = t & 1;

        const float2 oc = oR[t & 3];
        if (t + 4 < T)
            oR[t & 3] = __ldcs(reinterpret_cast<const float2*>(ob + (size_t)(t + 4) * S));

        // observation factor early (MUFU latency hides under the matvec)
        const float p0 = ex2f_(oc.x * LOG2E_F);
        const float p1 = ex2f_(oc.y * LOG2E_F);

        // fold previous publish's exact 2^-e every 8th step
        float sc = 1.0f;
        const bool fold = (t & 7) == 1;
        if (fold) {
            const float m = fmaxf(fmaxf(fmaxf(wm[h][0], wm[h][1]), fmaxf(wm[h][2], wm[h][3])),
                                  fmaxf(fmaxf(wm[h][4], wm[h][5]), fmaxf(wm[h][6], wm[h][7])));
            const int e = ((__float_as_int(m) >> 23) & 0xFF) - 127;
            L += e;
            sc = __int_as_float((127 - e) << 23);   // exact 2^-e
        }

        // matvec over this thread's 32-i chunk: 16 LDS.64, 4 fma2 chains
        const unsigned long long* V =
            reinterpret_cast<const unsigned long long*>(&v_sm[h][cb][ich * CH]);
        unsigned long long c0a = 0ull, c0b = 0ull, c1a = 0ull, c1b = 0ull;
#pragma unroll
        for (int k = 0; k < 8; ++k) {
            const unsigned long long va = V[2 * k], vb = V[2 * k + 1];
            fma2_(c0a, va, A0[2 * k]);
            fma2_(c1a, va, A1[2 * k]);
            fma2_(c0b, vb, A0[2 * k + 1]);
            fma2_(c1b, vb, A1[2 * k + 1]);
        }
        float x0, y0, x1, y1;
        upk2(add2_(c0a, c0b), x0, y0);
        upk2(add2_(c1a, c1b), x1, y1);
        float acc0 = x0 + y0;
        float acc1 = x1 + y1;
        // butterfly across the 4 i-chunks (lane^1, lane^2 flip only ich)
        acc0 += __shfl_xor_sync(0xffffffffu, acc0, 1);
        acc1 += __shfl_xor_sync(0xffffffffu, acc1, 1);
        acc0 += __shfl_xor_sync(0xffffffffu, acc0, 2);
        acc1 += __shfl_xor_sync(0xffffffffu, acc1, 2);

        const float un0 = fold ? acc0 * (p0 * sc) : acc0 * p0;
        const float un1 = fold ? acc1 * (p1 * sc) : acc1 * p1;

        // publish half-block max every 8th step (consumed at t+1)
        if ((t & 7) == 0) {
            const int im = __reduce_max_sync(0xffffffffu, __float_as_int(fmaxf(un0, un1)));
            if ((lt & 31) == 0) wm[h][lwrp] = __int_as_float(im);
        }
        if (ich == 0) {
            float2 w; w.x = un0; w.y = un1;
            *reinterpret_cast<float2*>(&v_sm[h][nb][wslot]) = w;
        }
        __syncthreads();
    }

    // ---- finalize per half: out[b] = -ln2 * (log2(sum_j v_j) + L) ----
    const int fb = (T - 1) & 1;
    float vv = 0.f;
    if (lt < 128) vv = v_sm[h][fb][((lt >> 5) * CH) + (lt & 31)];
#pragma unroll
    for (int o = 16; o; o >>= 1) vv += __shfl_xor_sync(0xffffffffu, vv, o);
    if (lt < 128 && (lt & 31) == 0) wsum[h][lt >> 5] = vv;
    __syncthreads();
    if (lt == 0) {
        const float s = (wsum[h][0] + wsum[h][1]) + (wsum[h][2] + wsum[h][3]);
        out[b] = -LN2_F * (lg2f_(s) + (float)L);
    }
}

extern "C" void kernel_launch(void* const* d_in, const int* in_sizes, int n_in,
                              void* d_out, int out_size)
{
    const float* obs  = (const float*)d_in[0];   // [B, T, S] f32
    const float* logA = (const float*)d_in[1];   // [S, S]   f32
    float* out = (float*)d_out;                  // [B]      f32

    const int B = out_size;
    const int S = 128;
    const int T = in_sizes[0] / (B * S);

    const int grid = (B + 1) / 2;
    crf_fwd_kernel<<<grid, 512>>>(obs, logA, out, T, B);
}

// round 8
// speedup vs baseline: 1.7855x; 1.7855x over previous
#include <cuda_runtime.h>
#include <cstdint>
#include <cstddef>

#define LOG2E_F 1.4426950408889634f
#define LN2_F   0.6931471805599453f

__device__ __forceinline__ float ex2f_(float x) {
    float y; asm("ex2.approx.ftz.f32 %0, %1;" : "=f"(y) : "f"(x)); return y;
}
__device__ __forceinline__ float lg2f_(float x) {
    float y; asm("lg2.approx.f32 %0, %1;" : "=f"(y) : "f"(x)); return y;
}
__device__ __forceinline__ unsigned long long pk2(float lo, float hi) {
    unsigned long long r; asm("mov.b64 %0, {%1, %2};" : "=l"(r) : "f"(lo), "f"(hi)); return r;
}
__device__ __forceinline__ void upk2(unsigned long long v, float& lo, float& hi) {
    asm("mov.b64 {%0, %1}, %2;" : "=f"(lo), "=f"(hi) : "l"(v));
}
__device__ __forceinline__ void fma2_(unsigned long long& acc, unsigned long long a, unsigned long long b) {
    asm("fma.rn.f32x2 %0, %1, %2, %0;" : "+l"(acc) : "l"(a), "l"(b));
}
__device__ __forceinline__ unsigned long long add2_(unsigned long long a, unsigned long long b) {
    unsigned long long r; asm("add.rn.f32x2 %0, %1, %2;" : "=l"(r) : "l"(a), "l"(b)); return r;
}

// One CTA per batch, 256 threads (8 warps). cp = tid>>2 -> column pair
// (j0 = 2cp, j0+1), ich = tid&3 -> 32-wide "from"-chunk. E = exp(logA) in
// registers as i-pair packed f32x2. Forward vector linear-domain in
// double-buffered smem, chunk stride 36 floats (144B: 16B-aligned so the
// matvec reads are 8x LDS.128 per thread -- halves the smem crossbar
// serialization vs 16x LDS.64 -- and the 4 chunk base addresses land on
// banks 0/4/8/12: conflict-free). Each 16B load feeds 4 fma.rn.f32x2
// directly. Exact power-of-2 renorm every 8 steps (publish block max at
// t%8==0, fold 2^-e at t%8==1). One __syncthreads per step. obs streamed
// via a 4-deep register prefetch ring.
__global__ __launch_bounds__(256, 1)
void crf_fwd_kernel(const float* __restrict__ obs,
                    const float* __restrict__ logA,
                    float* __restrict__ out,
                    int T)
{
    constexpr int S  = 128;
    constexpr int CH = 36;     // chunk stride (floats): 16B-aligned, bank-skewed
    __shared__ __align__(16) float v_sm[2][4 * CH];
    __shared__ float wm[8];
    __shared__ float wsum[4];

    const int tid  = threadIdx.x;
    const int b    = blockIdx.x;
    const int cp   = tid >> 2;
    const int ich  = tid & 3;
    const int j0   = cp * 2;
    const int warp = tid >> 5;
    const int wslot = ((j0 >> 5) * CH) + (j0 & 31);

    const float* ob = obs + (size_t)b * (size_t)T * S + j0;

    // A0[k] = {E[i0+2k][j0],   E[i0+2k+1][j0]}
    // A1[k] = {E[i0+2k][j0+1], E[i0+2k+1][j0+1]},  i0 = 32*ich
    unsigned long long A0[16], A1[16];
#pragma unroll
    for (int k = 0; k < 16; ++k) {
        const int i0 = ich * 32 + 2 * k;
        const float2 ea = *reinterpret_cast<const float2*>(logA + (size_t)i0 * S + j0);
        const float2 eb = *reinterpret_cast<const float2*>(logA + (size_t)(i0 + 1) * S + j0);
        A0[k] = pk2(ex2f_(ea.x * LOG2E_F), ex2f_(eb.x * LOG2E_F));
        A1[k] = pk2(ex2f_(ea.y * LOG2E_F), ex2f_(eb.y * LOG2E_F));
    }

    // ---- t = 0 (t%8==0): u = exp(obs[0]) raw; publish block max ----
    const float2 o0 = *reinterpret_cast<const float2*>(ob);
    const float u0 = ex2f_(o0.x * LOG2E_F);
    const float u1 = ex2f_(o0.y * LOG2E_F);
    {
        const int im = __reduce_max_sync(0xffffffffu, __float_as_int(fmaxf(u0, u1)));
        if ((tid & 31) == 0) wm[warp] = __int_as_float(im);
        if (ich == 0) {
            float2 w; w.x = u0; w.y = u1;
            *reinterpret_cast<float2*>(&v_sm[0][wslot]) = w;
        }
    }

    // 4-deep obs prefetch ring: oR[t & 3] holds obs[t].
    float2 oR[4];
#pragma unroll
    for (int k = 1; k <= 4; ++k)
        oR[k & 3] = (k < T) ? __ldcs(reinterpret_cast<const float2*>(ob + (size_t)k * S)) : o0;

    int L = 0;                 // exact accumulated log2 scale (uniform across block)
    __syncthreads();

    // ---- scan t = 1 .. T-1, ONE barrier per step ----
#pragma unroll 4
    for (int t = 1; t < T; ++t) {
        const int cb = (t - 1) & 1, nb = t & 1;

        const float2 oc = oR[t & 3];
        if (t + 4 < T)
            oR[t & 3] = __ldcs(reinterpret_cast<const float2*>(ob + (size_t)(t + 4) * S));

        // observation factor early (MUFU latency hides under the matvec)
        const float p0 = ex2f_(oc.x * LOG2E_F);
        const float p1 = ex2f_(oc.y * LOG2E_F);

        // fold previous publish's exact 2^-e every 8th step
        float sc = 1.0f;
        const bool fold = (t & 7) == 1;
        if (fold) {
            const float m = fmaxf(fmaxf(fmaxf(wm[0], wm[1]), fmaxf(wm[2], wm[3])),
                                  fmaxf(fmaxf(wm[4], wm[5]), fmaxf(wm[6], wm[7])));
            const int e = ((__float_as_int(m) >> 23) & 0xFF) - 127;
            L += e;
            sc = __int_as_float((127 - e) << 23);   // exact 2^-e
        }

        // matvec over this thread's 32-i chunk: 8x LDS.128, 4 fma2 chains
        const ulonglong2* V =
            reinterpret_cast<const ulonglong2*>(&v_sm[cb][ich * CH]);
        unsigned long long c0a = 0ull, c0b = 0ull, c1a = 0ull, c1b = 0ull;
#pragma unroll
        for (int k = 0; k < 8; ++k) {
            const ulonglong2 vv = V[k];
            fma2_(c0a, vv.x, A0[2 * k]);
            fma2_(c1a, vv.x, A1[2 * k]);
            fma2_(c0b, vv.y, A0[2 * k + 1]);
            fma2_(c1b, vv.y, A1[2 * k + 1]);
        }
        float x0, y0, x1, y1;
        upk2(add2_(c0a, c0b), x0, y0);
        upk2(add2_(c1a, c1b), x1, y1);
        float acc0 = x0 + y0;
        float acc1 = x1 + y1;
        // butterfly across the 4 i-chunks (lane^1, lane^2 flip only ich)
        acc0 += __shfl_xor_sync(0xffffffffu, acc0, 1);
        acc1 += __shfl_xor_sync(0xffffffffu, acc1, 1);
        acc0 += __shfl_xor_sync(0xffffffffu, acc0, 2);
        acc1 += __shfl_xor_sync(0xffffffffu, acc1, 2);

        const float un0 = fold ? acc0 * (p0 * sc) : acc0 * p0;
        const float un1 = fold ? acc1 * (p1 * sc) : acc1 * p1;

        // write v first (STS has no result latency; consumers gated by the bar)
        if (ich == 0) {
            float2 w; w.x = un0; w.y = un1;
            *reinterpret_cast<float2*>(&v_sm[nb][wslot]) = w;
        }
        // publish block max every 8th step (consumed at t+1)
        if ((t & 7) == 0) {
            const int im = __reduce_max_sync(0xffffffffu, __float_as_int(fmaxf(un0, un1)));
            if ((tid & 31) == 0) wm[warp] = __int_as_float(im);
        }
        __syncthreads();
    }

    // ---- finalize: out[b] = -ln2 * (log2(sum_j v_j) + L) ----
    const int fb = (T - 1) & 1;
    float vv = 0.f;
    if (tid < 128) vv = v_sm[fb][((tid >> 5) * CH) + (tid & 31)];
#pragma unroll
    for (int o = 16; o; o >>= 1) vv += __shfl_xor_sync(0xffffffffu, vv, o);
    if (tid < 128 && (tid & 31) == 0) wsum[tid >> 5] = vv;
    __syncthreads();
    if (tid == 0) {
        const float s = (wsum[0] + wsum[1]) + (wsum[2] + wsum[3]);
        out[b] = -LN2_F * (lg2f_(s) + (float)L);
    }
}

extern "C" void kernel_launch(void* const* d_in, const int* in_sizes, int n_in,
                              void* d_out, int out_size)
{
    const float* obs  = (const float*)d_in[0];   // [B, T, S] f32
    const float* logA = (const float*)d_in[1];   // [S, S]   f32
    float* out = (float*)d_out;                  // [B]      f32

    const int B = out_size;
    const int S = 128;
    const int T = in_sizes[0] / (B * S);

    crf_fwd_kernel<<<B, 256>>>(obs, logA, out, T);
}